// round 1
// baseline (speedup 1.0000x reference)
#include <cuda_runtime.h>
#include <cuda_fp16.h>

// Problem: B=16 batches of 512x512 grids.
// Pipeline:
//   setup:   x_mix -> u0 (bc at Dirichlet pts, 0 elsewhere), c mask (0.25 fluid / 0 dir, fp16),
//            base = w_outer * (geom<=0.5) * res_scale * (x_norm @ w_back + b) - y_mean/(y_std+eps)
//   50x jacobi: u' = u + c*(s - 4u)   (ping-pong g_u0 <-> g_u1)
//   final:   out = u * 1/(y_std+eps) + base

#define NB    16
#define NRES  512
#define NPTS  (NB * NRES * NRES)     // 4,194,304
#define NGRP  (NPTS / 4)             // float4 groups
#define NROWS (NB * NRES)            // 8192 global rows

__device__ float  g_u0[NPTS];
__device__ float  g_u1[NPTS];
__device__ __half g_c[NPTS];
__device__ float  g_base[NPTS];

__global__ __launch_bounds__(256) void setup_kernel(
        const float4* __restrict__ xmix,
        const float*  __restrict__ w_back,
        const float*  __restrict__ b_back,
        const float*  __restrict__ logit,
        const float*  __restrict__ y_mean,
        const float*  __restrict__ y_std) {
    int idx = blockIdx.x * blockDim.x + threadIdx.x;
    if (idx >= NPTS) return;
    int x = idx & (NRES - 1);
    int y = (idx >> 9) & (NRES - 1);

    float4 xm  = xmix[idx];            // [x0, x1, geom, bc]
    float geom = xm.z;
    float bc   = xm.w;
    bool solid = geom > 0.5f;
    bool edge  = (x == 0) | (x == NRES - 1) | (y == 0) | (y == NRES - 1);
    bool dir   = edge | solid;

    g_u0[idx] = dir ? bc : 0.0f;
    g_c[idx]  = __float2half(dir ? 0.0f : 0.25f);   // 0.25 exact in fp16

    // w_outer: linspace(0,1,512) -> i/511; min distance to any edge, /DELTA, clipped
    float xs = (float)y * (1.0f / 511.0f);
    float ys = (float)x * (1.0f / 511.0f);
    float d  = fminf(fminf(xs, 1.0f - xs), fminf(ys, 1.0f - ys));
    float w  = fminf(fmaxf(d * 20.0f, 0.0f), 1.0f);   // 1/DELTA = 20
    if (solid) w = 0.0f;

    float r   = fmaf(xm.x, w_back[0], fmaf(xm.y, w_back[1], b_back[0]));
    float rs  = 0.25f / (1.0f + __expf(-logit[0]));   // RES_SCALE_MAX * sigmoid
    float inv = 1.0f / (y_std[0] + 1e-5f);
    g_base[idx] = w * rs * r - y_mean[0] * inv;
}

// 2-D tiled Jacobi pass: block = 1024 threads = 128 col-groups x 8 rows
// (full 512-col rows per CTA -> no horizontal L2 halo; vertical halo 10/8).
__global__ __launch_bounds__(1024) void jacobi_kernel(int parity) {
    const float* __restrict__ usrc = parity ? g_u1 : g_u0;
    float*       __restrict__ udst = parity ? g_u0 : g_u1;

    int tid = threadIdx.x;
    int xg  = tid & 127;                       // float4 group within row
    int row = blockIdx.x * 8 + (tid >> 7);     // global row (batch-major)
    int y   = row & (NRES - 1);                // row within image
    int g   = row * 128 + xg;                  // float4 index
    int base = g * 4;                          // scalar index

    const float4* u4 = (const float4*)usrc;
    float4 ce = u4[g];
    float4 up = u4[(y == 0)        ? g : g - 128];  // clamped reads only feed
    float4 dn = u4[(y == NRES - 1) ? g : g + 128];  // Dirichlet lanes (c=0)
    float  le = (xg == 0)   ? ce.x : __ldg(&usrc[base - 1]);
    float  ri = (xg == 127) ? ce.w : __ldg(&usrc[base + 4]);

    const __half2* c2 = (const __half2*)(g_c + base);
    float2 cA = __half22float2(c2[0]);
    float2 cB = __half22float2(c2[1]);

    float s0 = (le   + ce.y) + (up.x + dn.x);
    float s1 = (ce.x + ce.z) + (up.y + dn.y);
    float s2 = (ce.y + ce.w) + (up.z + dn.z);
    float s3 = (ce.z + ri  ) + (up.w + dn.w);

    float4 o;
    o.x = fmaf(cA.x, fmaf(-4.0f, ce.x, s0), ce.x);  // fluid: 0.25*s ; dir: passthrough
    o.y = fmaf(cA.y, fmaf(-4.0f, ce.y, s1), ce.y);
    o.z = fmaf(cB.x, fmaf(-4.0f, ce.z, s2), ce.z);
    o.w = fmaf(cB.y, fmaf(-4.0f, ce.w, s3), ce.w);

    ((float4*)udst)[g] = o;
}

__global__ __launch_bounds__(256) void final_kernel(
        float* __restrict__ out,
        const float* __restrict__ y_std) {
    int gidx = blockIdx.x * blockDim.x + threadIdx.x;
    if (gidx >= NGRP) return;
    float inv = 1.0f / (y_std[0] + 1e-5f);
    const float4* u4 = (const float4*)g_u0;
    const float4* b4 = (const float4*)g_base;
    float4 u = u4[gidx];
    float4 b = b4[gidx];
    float4 o;
    o.x = fmaf(u.x, inv, b.x);
    o.y = fmaf(u.y, inv, b.y);
    o.z = fmaf(u.z, inv, b.z);
    o.w = fmaf(u.w, inv, b.w);
    ((float4*)out)[gidx] = o;
}

extern "C" void kernel_launch(void* const* d_in, const int* in_sizes, int n_in,
                              void* d_out, int out_size) {
    const float4* xmix   = (const float4*)d_in[0];
    const float*  w_back = (const float*)d_in[1];
    const float*  b_back = (const float*)d_in[2];
    const float*  logit  = (const float*)d_in[3];
    const float*  y_mean = (const float*)d_in[4];
    const float*  y_std  = (const float*)d_in[5];

    setup_kernel<<<NPTS / 256, 256>>>(xmix, w_back, b_back, logit, y_mean, y_std);

    for (int i = 0; i < 50; i++)
        jacobi_kernel<<<NROWS / 8, 1024>>>(i & 1);   // ends with result in g_u0

    final_kernel<<<NGRP / 256, 256>>>((float*)d_out, y_std);
}

// round 3
// speedup vs baseline: 1.9434x; 1.9434x over previous
#include <cuda_runtime.h>

// B=16 images of 512x512, 50 Jacobi iterations of masked 5-pt stencil.
// Temporal blocking: 5 kernels x 10 fused steps, state in registers.
//   CTA = 64 output rows x 512 cols of one image; loads 84 rows (10-row halo).
//   384 threads = 32 lanes (16 cols each, full row per warp) x 12 ty (7 rows each).
//   Horizontal neighbors: registers + warp shuffle. Vertical: smem boundary-row
//   exchange per step. Masked update is a bitwise select (garbage-immune).

#define NB    16
#define NRES  512
#define NPTS  (NB * NRES * NRES)
#define NGRP  (NPTS / 4)

#define KFUSE   10
#define TROWS   64
#define LROWS   (TROWS + 2 * KFUSE)   // 84
#define NTY     12
#define RPT     (LROWS / NTY)         // 7
#define THREADS (NTY * 32)            // 384
#define NTILES  (NRES / TROWS)        // 8

__device__ float         g_u0[NPTS];
__device__ float         g_u1[NPTS];
__device__ unsigned char g_m[NGRP];   // bit j of byte g = fluid(point 4g+j)
__device__ float         g_base[NPTS];

__global__ __launch_bounds__(256) void setup_kernel(
        const float4* __restrict__ xmix,
        const float*  __restrict__ w_back,
        const float*  __restrict__ b_back,
        const float*  __restrict__ logit,
        const float*  __restrict__ y_mean,
        const float*  __restrict__ y_std) {
    int g = blockIdx.x * blockDim.x + threadIdx.x;
    if (g >= NGRP) return;
    int xg  = g & 127;
    int row = g >> 7;
    int y   = row & (NRES - 1);
    int x0  = xg * 4;

    float rs  = 0.25f / (1.0f + __expf(-logit[0]));
    float inv = 1.0f / (y_std[0] + 1e-5f);
    float ofs = -y_mean[0] * inv;
    float w0  = w_back[0], w1 = w_back[1], bb = b_back[0];
    float ys  = (float)y * (1.0f / 511.0f);
    float wy  = fminf(ys, 1.0f - ys);

    float4 u0, base;
    float* up = &u0.x;
    float* bp = &base.x;
    unsigned mask = 0;
    #pragma unroll
    for (int i = 0; i < 4; i++) {
        int x = x0 + i;
        float4 xm = xmix[g * 4 + i];             // [x0, x1, geom, bc]
        bool solid = xm.z > 0.5f;
        bool edge  = (x == 0) | (x == NRES - 1) | (y == 0) | (y == NRES - 1);
        bool dir   = edge | solid;
        up[i] = dir ? xm.w : 0.0f;
        if (!dir) mask |= (1u << i);

        float xs = (float)x * (1.0f / 511.0f);
        float d  = fminf(wy, fminf(xs, 1.0f - xs));
        float w  = fminf(fmaxf(d * 20.0f, 0.0f), 1.0f);
        if (solid) w = 0.0f;
        float r = fmaf(xm.x, w0, fmaf(xm.y, w1, bb));
        bp[i] = fmaf(w * rs, r, ofs);
    }
    ((float4*)g_u0)[g]   = u0;
    ((float4*)g_base)[g] = base;
    g_m[g] = (unsigned char)mask;
}

// bitwise masked select: fluid -> fl, dirichlet -> ol  (k = compile-time bit index)
__device__ __forceinline__ float msel(float fl, float ol, unsigned m, int k) {
    int M = ((int)(m << (31 - k))) >> 31;
    return __int_as_float((__float_as_int(fl) & M) | (__float_as_int(ol) & ~M));
}

// one float4 group update; gi = group index within thread (compile-time)
__device__ __forceinline__ float4 upd4(float4 c, float4 U, float4 D,
                                       float L, float R, unsigned m, int gi) {
    float4 s;
    s.x = (L   + c.y) + (U.x + D.x);
    s.y = (c.x + c.z) + (U.y + D.y);
    s.z = (c.y + c.w) + (U.z + D.z);
    s.w = (c.z + R  ) + (U.w + D.w);
    float4 o;
    o.x = msel(0.25f * s.x, c.x, m, gi * 8 + 0);
    o.y = msel(0.25f * s.y, c.y, m, gi * 8 + 1);
    o.z = msel(0.25f * s.z, c.z, m, gi * 8 + 2);
    o.w = msel(0.25f * s.w, c.w, m, gi * 8 + 3);
    return o;
}

__global__ __launch_bounds__(THREADS, 1) void jacobi10_kernel(int parity) {
    const float4* __restrict__ src = parity ? (const float4*)g_u1 : (const float4*)g_u0;
    float4*       __restrict__ dst = parity ? (float4*)g_u0       : (float4*)g_u1;

    __shared__ float4 sb[2][4][THREADS];   // [bot/top][float4 idx][thread] = 48KB

    int tid  = threadIdx.x;
    int lane = tid & 31;
    int ty   = tid >> 5;                   // 0..11
    int img  = blockIdx.x >> 3;
    int tile = blockIdx.x & (NTILES - 1);
    int lr0  = tile * TROWS - KFUSE;       // image-row of local row 0 (may be <0)

    // ---- load 7 rows x 4 float4 + mask words (clamped to image) ----
    float4   v[RPT][4];
    unsigned mrow[RPT];
    #pragma unroll
    for (int r = 0; r < RPT; r++) {
        int lr = lr0 + ty * RPT + r;
        lr = min(max(lr, 0), NRES - 1);    // clamped rows are all-Dirichlet
        int grow = img * NRES + lr;
        int gi   = grow * 128 + lane * 4;
        v[r][0] = src[gi + 0];
        v[r][1] = src[gi + 1];
        v[r][2] = src[gi + 2];
        v[r][3] = src[gi + 3];
        mrow[r] = *reinterpret_cast<const unsigned*>(g_m + (size_t)grow * 128 + lane * 4);
    }

    // ---- 10 fused Jacobi steps ----
    for (int s = 0; s < KFUSE; s++) {
        // publish old boundary rows
        #pragma unroll
        for (int i = 0; i < 4; i++) {
            sb[0][i][tid] = v[RPT - 1][i];   // bot
            sb[1][i][tid] = v[0][i];         // top
        }
        __syncthreads();
        float4 above[4], below[4];
        #pragma unroll
        for (int i = 0; i < 4; i++) {
            above[i] = (ty == 0)       ? v[0][i]       : sb[0][i][tid - 32];
            below[i] = (ty == NTY - 1) ? v[RPT - 1][i] : sb[1][i][tid + 32];
        }
        __syncthreads();   // reads done before next step's publish

        float4 p0 = above[0], p1 = above[1], p2 = above[2], p3 = above[3];
        #pragma unroll
        for (int r = 0; r < RPT; r++) {
            float4 d0, d1, d2, d3;
            if (r == RPT - 1) { d0 = below[0]; d1 = below[1]; d2 = below[2]; d3 = below[3]; }
            else              { d0 = v[r + 1][0]; d1 = v[r + 1][1]; d2 = v[r + 1][2]; d3 = v[r + 1][3]; }

            float le = __shfl_up_sync(0xFFFFFFFFu, v[r][3].w, 1);   // lane0: image edge (Dirichlet)
            float ri = __shfl_down_sync(0xFFFFFFFFu, v[r][0].x, 1); // lane31: image edge

            unsigned m = mrow[r];
            float4 n0 = upd4(v[r][0], p0, d0, le,        v[r][1].x, m, 0);
            float4 n1 = upd4(v[r][1], p1, d1, v[r][0].w, v[r][2].x, m, 1);
            float4 n2 = upd4(v[r][2], p2, d2, v[r][1].w, v[r][3].x, m, 2);
            float4 n3 = upd4(v[r][3], p3, d3, v[r][2].w, ri,        m, 3);

            p0 = v[r][0]; p1 = v[r][1]; p2 = v[r][2]; p3 = v[r][3];
            v[r][0] = n0; v[r][1] = n1; v[r][2] = n2; v[r][3] = n3;
        }
    }

    // ---- store valid interior rows (local rows [KFUSE, KFUSE+TROWS)) ----
    #pragma unroll
    for (int r = 0; r < RPT; r++) {
        int lrl = ty * RPT + r;
        if (lrl >= KFUSE && lrl < KFUSE + TROWS) {
            int grow = img * NRES + lr0 + lrl;      // guaranteed in-range
            int gi   = grow * 128 + lane * 4;
            dst[gi + 0] = v[r][0];
            dst[gi + 1] = v[r][1];
            dst[gi + 2] = v[r][2];
            dst[gi + 3] = v[r][3];
        }
    }
}

__global__ __launch_bounds__(256) void final_kernel(
        float* __restrict__ out,
        const float* __restrict__ y_std) {
    int g = blockIdx.x * blockDim.x + threadIdx.x;
    if (g >= NGRP) return;
    float inv = 1.0f / (y_std[0] + 1e-5f);
    float4 u = ((const float4*)g_u1)[g];      // 5 ping-pong kernels end in g_u1
    float4 b = ((const float4*)g_base)[g];
    float4 o;
    o.x = fmaf(u.x, inv, b.x);
    o.y = fmaf(u.y, inv, b.y);
    o.z = fmaf(u.z, inv, b.z);
    o.w = fmaf(u.w, inv, b.w);
    ((float4*)out)[g] = o;
}

extern "C" void kernel_launch(void* const* d_in, const int* in_sizes, int n_in,
                              void* d_out, int out_size) {
    const float4* xmix   = (const float4*)d_in[0];
    const float*  w_back = (const float*)d_in[1];
    const float*  b_back = (const float*)d_in[2];
    const float*  logit  = (const float*)d_in[3];
    const float*  y_mean = (const float*)d_in[4];
    const float*  y_std  = (const float*)d_in[5];

    setup_kernel<<<NGRP / 256, 256>>>(xmix, w_back, b_back, logit, y_mean, y_std);

    for (int s = 0; s < 5; s++)                 // 5 x 10 = 50 iterations
        jacobi10_kernel<<<NB * NTILES, THREADS>>>(s & 1);

    final_kernel<<<NGRP / 256, 256>>>((float*)d_out, y_std);
}